// round 5
// baseline (speedup 1.0000x reference)
#include <cuda_runtime.h>
#include <cstdint>

// Problem constants (fixed by setup_inputs): B=1, H=32, Lq=512, Lk=4096, group_size=4
#define H       32
#define LQ      512
#define LK      4096
#define WORDS   128            // LK / 32
#define KSEL    819            // int(0.2 * 4096)
#define THRESH  1638           // min(2*819, int(0.75*4096))
#define GS      4
#define NG      8              // H / GS
#define NOT_CHOSEN (1 << 30)
#define MAXCAND 256

// Statistical window for the 819th-largest of 4096 i.i.d. N(0,1) samples.
// Quantile = 0.8416, sd of the order statistic ~0.022 -> [0.70, 1.00] is ~7 sigma.
// Exact fallback path handles anything outside the window.
#define WLO 0.70f
#define WHI 1.00f
#define WSCALE (256.0f / (WHI - WLO))

// Scratch (device globals; no allocation allowed)
__device__ unsigned g_masks[(size_t)H * LQ * WORDS];   // 8 MB of top-k bitsets
__device__ int      g_bmax[NG];      // per-block max chosen nsel
__device__ int      g_ball[NG];      // per-block "all heads chosen"
__device__ int      g_gcnt[NG];      // per-group popcount for density
__device__ int      g_done[NG];      // phase-1 flags (reset by k_topk block 0)
__device__ int      g_done2[NG];     // phase-2 flags (reset by k_topk block 0)

// Order-preserving float -> uint32 map (larger float => larger key)
__device__ __forceinline__ unsigned fkey(float f) {
    unsigned u = __float_as_uint(f);
    return (u & 0x80000000u) ? ~u : (u | 0x80000000u);
}

// ---------------------------------------------------------------------------
// Kernel 1: per-row exact top-k mask via windowed 256-bin histogram around the
// statistically-known pivot location + exact candidate refinement, with an
// exact 32-step binary-search fallback. Also zeros this row of the output
// with streaming stores, and resets k_tail's spin flags (block 0).
// grid = H*LQ blocks, 256 threads; each block owns one row of 4096 floats.
// ---------------------------------------------------------------------------
__global__ void __launch_bounds__(256) k_topk(const float* __restrict__ scores,
                                              float* __restrict__ out) {
    __shared__ unsigned hist[256];          // 1 KB windowed histogram
    __shared__ unsigned cand[MAXCAND];      // pivot-bin candidates (fkey)
    __shared__ unsigned char snib[1024];    // 4-bit membership nibbles
    __shared__ unsigned s_cnthi, s_ncand, s_pivotkey, s_tot;
    __shared__ int s_bin, s_rem;

    const int row = blockIdx.x;
    const int t   = threadIdx.x;
    const int lane = t & 31, warp = t >> 5;

    // Reset k_tail flags once per launch (kernel boundary orders this vs k_tail)
    if (row == 0 && t < NG) { g_done[t] = 0; g_done2[t] = 0; }

    hist[t] = 0u;
    if (t == 0) { s_cnthi = 0u; s_ncand = 0u; s_bin = -2; }
    __syncthreads();

    // Load 16 elements/thread (streaming, coalesced float4); zero the row.
    float x[16];
    const float4* src  = (const float4*)(scores + (size_t)row * LK);
    float4*       zdst = (float4*)(out + (size_t)row * LK);
    #pragma unroll
    for (int i = 0; i < 4; i++) {
        float4 v = __ldcs(src + t + i * 256);
        x[4 * i + 0] = v.x; x[4 * i + 1] = v.y;
        x[4 * i + 2] = v.z; x[4 * i + 3] = v.w;
    }
    const float4 z = make_float4(0.f, 0.f, 0.f, 0.f);
    #pragma unroll
    for (int i = 0; i < 4; i++) __stcs(zdst + t + i * 256, z);

    // Count above-window; histogram only the in-window elements (~8% of row)
    int chi = 0;
    #pragma unroll
    for (int e = 0; e < 16; e++) {
        float v = x[e];
        if (v > WHI) {
            chi++;
        } else if (v >= WLO) {
            int b = (int)((WHI - v) * WSCALE);
            if (b > 255) b = 255;
            atomicAdd(&hist[b], 1u);
        }
    }
    #pragma unroll
    for (int off = 16; off; off >>= 1)
        chi += __shfl_down_sync(0xffffffffu, chi, off);
    if (lane == 0) atomicAdd(&s_cnthi, (unsigned)chi);
    __syncthreads();

    // One-warp prefix scan over the 256 bins (bin 0 = largest values)
    if (warp == 0) {
        const unsigned cnthi = s_cnthi;
        unsigned part = 0;
        #pragma unroll
        for (int i = 0; i < 8; i++) part += hist[lane * 8 + i];
        unsigned pfx = part;
        #pragma unroll
        for (int s = 1; s < 32; s <<= 1) {
            unsigned v = __shfl_up_sync(0xffffffffu, pfx, s);
            if (lane >= s) pfx += v;
        }
        unsigned excl = pfx - part;
        unsigned total = __shfl_sync(0xffffffffu, pfx, 31);
        unsigned base = cnthi + excl;
        if (base < KSEL && base + part >= KSEL) {
            unsigned acc = base;
            #pragma unroll
            for (int i = 0; i < 8; i++) {
                unsigned hv = hist[lane * 8 + i];
                if (acc + hv >= KSEL) { s_bin = lane * 8 + i; s_rem = (int)(KSEL - acc); break; }
                acc += hv;
            }
        }
        if (lane == 0 && (cnthi >= KSEL || cnthi + total < KSEL)) s_bin = -1; // fallback
    }
    __syncthreads();

    const int bin = s_bin;

    if (bin >= 0) {
        // ---- fast path: gather candidates in the pivot bin, exact rank-select
        #pragma unroll
        for (int e = 0; e < 16; e++) {
            float v = x[e];
            if (v <= WHI && v >= WLO) {
                int b = (int)((WHI - v) * WSCALE);
                if (b > 255) b = 255;
                if (b == bin) {
                    unsigned p = atomicAdd(&s_ncand, 1u);
                    if (p < MAXCAND) cand[p] = fkey(v);
                }
            }
        }
        __syncthreads();
        unsigned nc = s_ncand;
        if (nc <= MAXCAND) {
            const int rem = s_rem;
            if (t < (int)nc) {
                unsigned me = cand[t];
                int gcnt = 0, eq = 0;
                for (unsigned j = 0; j < nc; j++) {
                    unsigned v = cand[j];
                    gcnt += (v > me);
                    eq   += (v == me);
                }
                if (gcnt < rem && gcnt + eq >= rem) s_pivotkey = me;
            }
        } else {
            if (t == 0) s_bin = -1;   // overflow -> fallback
        }
        __syncthreads();
    }

    if (s_bin < 0) {
        // ---- exact fallback: MSB-first binary search on order-preserving keys
        unsigned piv = 0;
        for (int bit = 31; bit >= 0; --bit) {
            unsigned candv = piv | (1u << bit);
            int c = 0;
            #pragma unroll
            for (int e = 0; e < 16; e++) c += (fkey(x[e]) >= candv);
            #pragma unroll
            for (int off = 16; off; off >>= 1)
                c += __shfl_down_sync(0xffffffffu, c, off);
            if (t == 0) s_tot = 0u;
            __syncthreads();
            if (lane == 0) atomicAdd(&s_tot, (unsigned)c);
            __syncthreads();
            if (s_tot >= KSEL) piv = candv;
            __syncthreads();
        }
        if (t == 0) s_pivotkey = piv;
        __syncthreads();
    }

    const unsigned pivot = s_pivotkey;

    // Membership nibbles: nib[n] holds bits for elements [4n, 4n+4)
    #pragma unroll
    for (int i = 0; i < 4; i++) {
        unsigned nib = 0;
        #pragma unroll
        for (int m = 0; m < 4; m++) nib |= (unsigned)(fkey(x[4 * i + m]) >= pivot) << m;
        snib[t + i * 256] = (unsigned char)nib;
    }
    __syncthreads();

    // Pack 8 nibbles -> one 32-bit mask word; 128 words per row
    if (t < 128) {
        unsigned lo = *(const unsigned*)&snib[8 * t];
        unsigned hi = *(const unsigned*)&snib[8 * t + 4];
        unsigned w =  (lo         & 0xFu)
                   | ((lo >>  8)  & 0xFu) << 4
                   | ((lo >> 16)  & 0xFu) << 8
                   | ((lo >> 24)  & 0xFu) << 12
                   | ( hi         & 0xFu) << 16
                   | ((hi >>  8)  & 0xFu) << 20
                   | ((hi >> 16)  & 0xFu) << 24
                   | ((hi >> 24)  & 0xFu) << 28;
        g_masks[(size_t)row * WORDS + t] = w;
    }
}

// ---------------------------------------------------------------------------
// Kernel 2 (fused tail): per-head back-to-front scans, global n_stop coupling
// via spin barrier (NG=8 blocks, always co-resident), group-OR, last-row
// writes, density. ALL __syncthreads() are executed unconditionally by all
// 256 threads (round-4 bug fix: no barriers under thread-id guards).
// grid = NG blocks, 256 threads.
// ---------------------------------------------------------------------------
__global__ void __launch_bounds__(256) k_tail(float* __restrict__ out, int write_density) {
    const int g = blockIdx.x, t = threadIdx.x;
    const int lane = t & 31, warp = t >> 5;
    __shared__ int s_found, s_cnt;
    __shared__ int ws[8];
    __shared__ int s_nsel[GS];
    __shared__ unsigned su[WORDS];
    __shared__ int s_nstop;

    // ---- Phase 1: nsel for this group's 4 heads. All threads iterate; the
    //      upper 128 threads contribute zero words so barriers stay aligned.
    for (int hh = 0; hh < GS; hh++) {
        const int h = g * GS + hh;
        if (t == 0) { s_found = 0; s_cnt = 0; }
        __syncthreads();
        const unsigned* base = g_masks + (size_t)h * LQ * WORDS;
        unsigned un = 0;
        for (int n = 1; n <= LQ; n++) {
            unsigned m = (t < 128) ? base[(size_t)(LQ - n) * WORDS + t] : 0u;
            int add = __popc(m & ~un);
            un |= m;
            #pragma unroll
            for (int off = 16; off; off >>= 1)
                add += __shfl_down_sync(0xffffffffu, add, off);
            if (lane == 0) ws[warp] = add;
            __syncthreads();
            if (t == 0) {
                int sum = 0;
                #pragma unroll
                for (int w = 0; w < 8; w++) sum += ws[w];
                s_cnt += sum;
                if (!s_found && s_cnt >= THRESH) s_found = n;
            }
            __syncthreads();
            if (s_found) break;          // uniform: decided from shared state
        }
        if (t == 0) s_nsel[hh] = s_found ? s_found : NOT_CHOSEN;
        __syncthreads();
    }

    // ---- Barrier 1: publish per-block max/all-chosen, wait for all blocks ----
    if (t == 0) {
        int mx = 1, all = 1;
        #pragma unroll
        for (int i = 0; i < GS; i++) {
            int v = s_nsel[i];
            if (v >= NOT_CHOSEN) all = 0;
            else if (v > mx) mx = v;
        }
        g_bmax[g] = mx;
        g_ball[g] = all;
        __threadfence();
        atomicExch(&g_done[g], 1);
    }
    if (t < NG) {
        volatile int* vd = g_done;
        while (vd[t] == 0) {}
    }
    __syncthreads();
    __threadfence();

    if (t == 0) {
        int mx = 1, all = 1;
        #pragma unroll
        for (int i = 0; i < NG; i++) {
            int v = g_bmax[i];
            if (v > mx) mx = v;
            all &= g_ball[i];
        }
        s_nstop = all ? mx : LQ;
    }
    __syncthreads();

    // ---- Phase 2: union of last n_stop rows for each head, group OR ----
    const int ns = s_nstop;
    if (t < 128) {
        unsigned u = 0;
        #pragma unroll
        for (int hh = 0; hh < GS; hh++) {
            const unsigned* base = g_masks + (size_t)(g * GS + hh) * LQ * WORDS;
            for (int n = 1; n <= ns; n++)
                u |= base[(size_t)(LQ - n) * WORDS + t];
        }
        su[t] = u;
        int c = __popc(u);
        #pragma unroll
        for (int off = 16; off; off >>= 1)
            c += __shfl_down_sync(0xffffffffu, c, off);
        if (lane == 0) ws[warp] = c;
    }
    __syncthreads();

    // ---- Output: last-row values for the 4 heads of this group ----
    const float MINV = -3.402823466e38f;  // finfo(float32).min
    #pragma unroll
    for (int j = 0; j < 16; j++) {
        int col = j * 256 + t;
        float val = ((su[col >> 5] >> (col & 31)) & 1u) ? 0.0f : MINV;
        #pragma unroll
        for (int hh = 0; hh < GS; hh++) {
            size_t off = ((size_t)(g * GS + hh) * LQ + (LQ - 1)) * LK + col;
            out[off] = val;
        }
    }

    // ---- Barrier 2 + density (block 0 writes the scalar) ----
    if (write_density) {
        if (t == 0) {
            g_gcnt[g] = GS * (ws[0] + ws[1] + ws[2] + ws[3]);
            __threadfence();
            atomicExch(&g_done2[g], 1);
        }
        if (t < NG) {
            volatile int* vd = g_done2;
            while (vd[t] == 0) {}
        }
        __syncthreads();
        __threadfence();
        if (g == 0 && t == 0) {
            int total = 0;
            #pragma unroll
            for (int i = 0; i < NG; i++) total += g_gcnt[i];
            out[(size_t)H * LQ * LK] = (float)total / (float)(H * LK);
        }
    }
}

// ---------------------------------------------------------------------------
extern "C" void kernel_launch(void* const* d_in, const int* in_sizes, int n_in,
                              void* d_out, int out_size) {
    const float* scores = (const float*)d_in[0];
    float* out = (float*)d_out;

    k_topk<<<H * LQ, 256>>>(scores, out);   // also zeros output rows + resets flags
    k_tail<<<NG, 256>>>(out, out_size > H * LQ * LK ? 1 : 0);
}

// round 6
// speedup vs baseline: 1.1417x; 1.1417x over previous
#include <cuda_runtime.h>
#include <cstdint>

// Problem constants (fixed by setup_inputs): B=1, H=32, Lq=512, Lk=4096, group_size=4
#define H       32
#define LQ      512
#define LK      4096
#define WORDS   128            // LK / 32
#define KSEL    819            // int(0.2 * 4096)
#define THRESH  1638           // min(2*819, int(0.75*4096))
#define GS      4
#define NG      8              // H / GS
#define NOT_CHOSEN (1 << 30)
#define MAXCAND 64

// Key-domain window for the 819th-largest of 4096 i.i.d. N(0,1) samples.
// Pivot value concentrates at 0.8416 +- 0.022; window [0.70, 1.00] is ~7 sigma.
// fkey is linear in value on [0.5, 1.0) (one exponent region), so key-binning
// is exact value-binning. Exact fallback handles anything outside the window.
#define KHI 0xBF800000u        // fkey(1.0f)
#define KLO 0xBF333333u        // fkey(0.7f)
#define BSHIFT 14              // bin width = 2^14 keys = 2^-10 in value
#define NBIN 308               // ((KHI-KLO)>>BSHIFT)+1
#define HSIZE 320              // padded: 10 bins/lane * 32 lanes
#define BPL 10

// Scratch (device globals; no allocation allowed)
__device__ unsigned g_masks[(size_t)H * LQ * WORDS];   // 8 MB of top-k bitsets
__device__ unsigned g_hunion[H * WORDS];
__device__ int      g_nsel[H];
__device__ int      g_gcnt[NG];
__device__ int      g_done[H];       // barrier-1 flags (reset by k_topk block 0)
__device__ int      g_done2[H];      // barrier-2 flags
__device__ int      g_done3[NG];     // density flags

// Order-preserving float -> uint32 map (larger float => larger key)
__device__ __forceinline__ unsigned fkey(float f) {
    unsigned u = __float_as_uint(f);
    return (u & 0x80000000u) ? ~u : (u | 0x80000000u);
}

// ---------------------------------------------------------------------------
// Kernel 1: per-row exact top-k mask. Single windowed 308-bin key-domain
// histogram + tiny exact refinement (expected ~1 candidate/bin), exact
// binary-search fallback. Zeros this row of the output. 5 block barriers.
// grid = H*LQ blocks, 256 threads; each block owns one row of 4096 floats.
// ---------------------------------------------------------------------------
__global__ void __launch_bounds__(256) k_topk(const float* __restrict__ scores,
                                              float* __restrict__ out) {
    __shared__ unsigned hist[HSIZE];
    __shared__ unsigned cand[MAXCAND];
    __shared__ unsigned s_cnthi, s_ncand, s_pivotkey, s_tot;
    __shared__ int s_bin, s_rem;

    const int row = blockIdx.x;
    const int t   = threadIdx.x;
    const int lane = t & 31, warp = t >> 5;

    // Reset k_tail flags once per launch (kernel boundary orders this vs k_tail)
    if (row == 0) {
        if (t < H)  { g_done[t] = 0; g_done2[t] = 0; }
        if (t < NG) g_done3[t] = 0;
    }

    hist[t] = 0u;
    if (t < HSIZE - 256) hist[256 + t] = 0u;
    if (t == 0) { s_cnthi = 0u; s_ncand = 0u; s_bin = -2; }
    __syncthreads();

    // Load 16 elements/thread as keys (coalesced float4); zero the output row.
    unsigned key[16];
    const float4* src  = (const float4*)(scores + (size_t)row * LK);
    float4*       zdst = (float4*)(out + (size_t)row * LK);
    #pragma unroll
    for (int i = 0; i < 4; i++) {
        float4 v = __ldcs(src + t + i * 256);
        key[4 * i + 0] = fkey(v.x); key[4 * i + 1] = fkey(v.y);
        key[4 * i + 2] = fkey(v.z); key[4 * i + 3] = fkey(v.w);
    }
    const float4 z = make_float4(0.f, 0.f, 0.f, 0.f);
    #pragma unroll
    for (int i = 0; i < 4; i++) __stcs(zdst + t + i * 256, z);

    // Count above-window; histogram in-window keys (~8% of row)
    int chi = 0;
    #pragma unroll
    for (int e = 0; e < 16; e++) {
        unsigned k = key[e];
        if (k > KHI) chi++;
        else if (k >= KLO) atomicAdd(&hist[(KHI - k) >> BSHIFT], 1u);
    }
    #pragma unroll
    for (int off = 16; off; off >>= 1)
        chi += __shfl_down_sync(0xffffffffu, chi, off);
    if (lane == 0) atomicAdd(&s_cnthi, (unsigned)chi);
    __syncthreads();

    // One-warp cumulative-from-top scan over the bins (bin 0 = largest values)
    if (warp == 0) {
        const unsigned cnthi = s_cnthi;
        unsigned part = 0;
        #pragma unroll
        for (int i = 0; i < BPL; i++) part += hist[lane * BPL + i];
        unsigned pfx = part;
        #pragma unroll
        for (int s = 1; s < 32; s <<= 1) {
            unsigned v = __shfl_up_sync(0xffffffffu, pfx, s);
            if (lane >= s) pfx += v;
        }
        unsigned excl  = pfx - part;
        unsigned total = __shfl_sync(0xffffffffu, pfx, 31);
        unsigned base  = cnthi + excl;
        if (base < KSEL && base + part >= KSEL) {
            unsigned acc = base;
            #pragma unroll
            for (int i = 0; i < BPL; i++) {
                unsigned hv = hist[lane * BPL + i];
                if (acc + hv >= KSEL) { s_bin = lane * BPL + i; s_rem = (int)(KSEL - acc); break; }
                acc += hv;
            }
        }
        if (lane == 0 && (cnthi >= KSEL || cnthi + total < KSEL)) s_bin = -1; // fallback
    }
    __syncthreads();

    const int bin = s_bin;

    if (bin >= 0) {
        // Gather pivot-bin candidates (expected ~1, bin width 2^-10 in value)
        #pragma unroll
        for (int e = 0; e < 16; e++) {
            unsigned k = key[e];
            if (k <= KHI && k >= KLO && (int)((KHI - k) >> BSHIFT) == bin) {
                unsigned p = atomicAdd(&s_ncand, 1u);
                if (p < MAXCAND) cand[p] = k;
            }
        }
        __syncthreads();
        unsigned nc = s_ncand;
        if (nc <= MAXCAND) {
            const int rem = s_rem;
            if (t < (int)nc) {
                unsigned me = cand[t];
                int gcnt = 0, eq = 0;
                for (unsigned j = 0; j < nc; j++) {
                    unsigned v = cand[j];
                    gcnt += (v > me);
                    eq   += (v == me);
                }
                if (gcnt < rem && gcnt + eq >= rem) s_pivotkey = me;
            }
        } else {
            if (t == 0) s_bin = -1;   // overflow -> fallback
        }
        __syncthreads();
    }

    if (s_bin < 0) {
        // Exact fallback: MSB-first binary search on keys
        unsigned piv = 0;
        for (int bit = 31; bit >= 0; --bit) {
            unsigned candv = piv | (1u << bit);
            int c = 0;
            #pragma unroll
            for (int e = 0; e < 16; e++) c += (key[e] >= candv);
            #pragma unroll
            for (int off = 16; off; off >>= 1)
                c += __shfl_down_sync(0xffffffffu, c, off);
            if (t == 0) s_tot = 0u;
            __syncthreads();
            if (lane == 0) atomicAdd(&s_tot, (unsigned)c);
            __syncthreads();
            if (s_tot >= KSEL) piv = candv;
            __syncthreads();
        }
        if (t == 0) s_pivotkey = piv;
        __syncthreads();
    }

    const unsigned pivot = s_pivotkey;

    // Membership: element 4t+1024i+m. Per i, each thread owns 4 consecutive
    // bits; OR-merge nibbles across each 8-lane octet with 3 xor-shuffles,
    // lane(octet leader) writes the 32-bit word. No smem, no barrier.
    unsigned* mrow = g_masks + (size_t)row * WORDS;
    #pragma unroll
    for (int i = 0; i < 4; i++) {
        unsigned nib = 0;
        #pragma unroll
        for (int m = 0; m < 4; m++) nib |= (unsigned)(key[4 * i + m] >= pivot) << m;
        unsigned wv = nib << (4 * (lane & 7));
        wv |= __shfl_xor_sync(0xffffffffu, wv, 1);
        wv |= __shfl_xor_sync(0xffffffffu, wv, 2);
        wv |= __shfl_xor_sync(0xffffffffu, wv, 4);
        if ((lane & 7) == 0) mrow[32 * i + 4 * warp + (lane >> 3)] = wv;
    }
}

// ---------------------------------------------------------------------------
// Kernel 2 (fused tail): one block per head (32 blocks, always co-resident).
// Phase 1: per-head back-to-front scan (parallel across heads). Spin barrier.
// n_stop. Phase 2: per-head union. Spin barrier. Group-OR + last-row write
// (spread over 32 blocks) + density. All __syncthreads() unconditional.
// ---------------------------------------------------------------------------
__global__ void __launch_bounds__(256) k_tail(float* __restrict__ out, int write_density) {
    const int h = blockIdx.x;          // 0..31
    const int g = h / GS;
    const int t = threadIdx.x;
    const int lane = t & 31, warp = t >> 5;
    __shared__ int s_found, s_cnt, s_nstop;
    __shared__ int ws[8];
    __shared__ unsigned su[WORDS];

    // ---- Phase 1: nsel for head h ----
    if (t == 0) { s_found = 0; s_cnt = 0; }
    __syncthreads();
    const unsigned* base = g_masks + (size_t)h * LQ * WORDS;
    unsigned un = 0;
    for (int n = 1; n <= LQ; n++) {
        unsigned m = (t < 128) ? base[(size_t)(LQ - n) * WORDS + t] : 0u;
        int add = __popc(m & ~un);
        un |= m;
        #pragma unroll
        for (int off = 16; off; off >>= 1)
            add += __shfl_down_sync(0xffffffffu, add, off);
        if (lane == 0) ws[warp] = add;
        __syncthreads();
        if (t == 0) {
            int sum = 0;
            #pragma unroll
            for (int w = 0; w < 8; w++) sum += ws[w];
            s_cnt += sum;
            if (!s_found && s_cnt >= THRESH) s_found = n;
        }
        __syncthreads();
        if (s_found) break;            // uniform: decided from shared state
    }
    if (t == 0) {
        g_nsel[h] = s_found ? s_found : NOT_CHOSEN;
        __threadfence();
        atomicExch(&g_done[h], 1);
    }

    // ---- Global barrier 1 (32 co-resident blocks) ----
    if (t < H) {
        volatile int* vd = g_done;
        while (vd[t] == 0) {}
    }
    __syncthreads();
    __threadfence();

    // n_stop from all heads (warp 0)
    if (warp == 0) {
        int v  = g_nsel[lane];
        int ch = (v < NOT_CHOSEN) ? 1 : 0;
        int mx = ch ? v : 1;
        #pragma unroll
        for (int off = 16; off; off >>= 1) {
            ch = min(ch, __shfl_down_sync(0xffffffffu, ch, off));
            mx = max(mx, __shfl_down_sync(0xffffffffu, mx, off));
        }
        if (lane == 0) s_nstop = ch ? mx : LQ;
    }
    __syncthreads();

    // ---- Phase 2: union of last n_stop rows of head h ----
    const int ns = s_nstop;
    if (t < 128) {
        unsigned u = 0;
        for (int n = 1; n <= ns; n++)
            u |= base[(size_t)(LQ - n) * WORDS + t];
        g_hunion[h * WORDS + t] = u;
    }
    __threadfence();
    __syncthreads();
    if (t == 0) atomicExch(&g_done2[h], 1);

    // ---- Global barrier 2 ----
    if (t < H) {
        volatile int* vd = g_done2;
        while (vd[t] == 0) {}
    }
    __syncthreads();
    __threadfence();

    // Group-OR for this head's group
    if (t < 128) {
        unsigned gu = g_hunion[(g * GS + 0) * WORDS + t]
                    | g_hunion[(g * GS + 1) * WORDS + t]
                    | g_hunion[(g * GS + 2) * WORDS + t]
                    | g_hunion[(g * GS + 3) * WORDS + t];
        su[t] = gu;
        int c = __popc(gu);
        #pragma unroll
        for (int off = 16; off; off >>= 1)
            c += __shfl_down_sync(0xffffffffu, c, off);
        if (lane == 0) ws[warp] = c;
    }
    __syncthreads();

    // Last-row values for head h (float4 stores, 16 KB per block)
    const float MINV = -3.402823466e38f;  // finfo(float32).min
    float* orow = out + ((size_t)h * LQ + (LQ - 1)) * LK;
    #pragma unroll
    for (int i = 0; i < 4; i++) {
        int c4 = t + i * 256;              // float4 index; cols 4*c4..4*c4+3
        unsigned w = su[c4 >> 3];
        float4 v;
        v.x = ((w >> ((4 * c4 + 0) & 31)) & 1u) ? 0.0f : MINV;
        v.y = ((w >> ((4 * c4 + 1) & 31)) & 1u) ? 0.0f : MINV;
        v.z = ((w >> ((4 * c4 + 2) & 31)) & 1u) ? 0.0f : MINV;
        v.w = ((w >> ((4 * c4 + 3) & 31)) & 1u) ? 0.0f : MINV;
        ((float4*)orow)[c4] = v;
    }

    // Density: one block per group publishes; block 0 aggregates
    if (write_density) {
        if ((h & (GS - 1)) == 0 && t == 0) {
            g_gcnt[g] = GS * (ws[0] + ws[1] + ws[2] + ws[3]);
            __threadfence();
            atomicExch(&g_done3[g], 1);
        }
        if (h == 0) {
            if (t < NG) {
                volatile int* vd = g_done3;
                while (vd[t] == 0) {}
            }
            __syncthreads();
            __threadfence();
            if (t == 0) {
                int total = 0;
                #pragma unroll
                for (int i = 0; i < NG; i++) total += g_gcnt[i];
                out[(size_t)H * LQ * LK] = (float)total / (float)(H * LK);
            }
        }
    }
}

// ---------------------------------------------------------------------------
extern "C" void kernel_launch(void* const* d_in, const int* in_sizes, int n_in,
                              void* d_out, int out_size) {
    const float* scores = (const float*)d_in[0];
    float* out = (float*)d_out;

    k_topk<<<H * LQ, 256>>>(scores, out);   // also zeros output rows + resets flags
    k_tail<<<H, 256>>>(out, out_size > H * LQ * LK ? 1 : 0);
}

// round 7
// speedup vs baseline: 1.1420x; 1.0003x over previous
#include <cuda_runtime.h>
#include <cstdint>

// Problem constants (fixed by setup_inputs): B=1, H=32, Lq=512, Lk=4096, group_size=4
#define H       32
#define LQ      512
#define LK      4096
#define WORDS   128            // LK / 32
#define KSEL    819            // int(0.2 * 4096)
#define THRESH  1638           // min(2*819, int(0.75*4096))
#define GS      4
#define NG      8              // H / GS
#define NOT_CHOSEN (1 << 30)
#define MAXCAND 64

// Key-domain window for the 819th-largest of 4096 i.i.d. N(0,1) samples.
// Pivot value concentrates at 0.8416 +- 0.022; window [0.70, 1.00] is ~7 sigma.
// fkey is linear in value on [0.5, 1.0) (one exponent region), so key-binning
// is exact value-binning. Exact fallback handles anything outside the window.
#define KHI 0xBF800000u        // fkey(1.0f)
#define KLO 0xBF333333u        // fkey(0.7f)
#define BSHIFT 14              // bin width = 2^14 keys = 2^-10 in value
#define NBIN 308               // ((KHI-KLO)>>BSHIFT)+1
#define HSIZE 320              // padded: 10 bins/lane * 32 lanes
#define BPL 10

// Scratch (device globals; no allocation allowed)
__device__ unsigned g_masks[(size_t)H * LQ * WORDS];   // 8 MB of top-k bitsets
__device__ unsigned g_hunion[H * WORDS];
__device__ int      g_nsel[H];
__device__ int      g_gcnt[NG];
__device__ int      g_done[H];       // barrier-1 flags (reset by k_topk block 0)
__device__ int      g_done2[H];      // barrier-2 flags
__device__ int      g_done3[NG];     // density flags

// Order-preserving float -> uint32 map (larger float => larger key)
__device__ __forceinline__ unsigned fkey(float f) {
    unsigned u = __float_as_uint(f);
    return (u & 0x80000000u) ? ~u : (u | 0x80000000u);
}

// ---------------------------------------------------------------------------
// Kernel 1: per-row exact top-k mask. Single windowed 308-bin key-domain
// histogram + tiny exact refinement (expected ~1 candidate/bin), exact
// binary-search fallback. Zeros this row of the output. 5 block barriers.
// grid = H*LQ blocks, 256 threads; each block owns one row of 4096 floats.
// ---------------------------------------------------------------------------
__global__ void __launch_bounds__(256) k_topk(const float* __restrict__ scores,
                                              float* __restrict__ out) {
    __shared__ unsigned hist[HSIZE];
    __shared__ unsigned cand[MAXCAND];
    __shared__ unsigned s_cnthi, s_ncand, s_pivotkey, s_tot;
    __shared__ int s_bin, s_rem;

    const int row = blockIdx.x;
    const int t   = threadIdx.x;
    const int lane = t & 31, warp = t >> 5;

    // Reset k_tail flags once per launch (kernel boundary orders this vs k_tail)
    if (row == 0) {
        if (t < H)  { g_done[t] = 0; g_done2[t] = 0; }
        if (t < NG) g_done3[t] = 0;
    }

    hist[t] = 0u;
    if (t < HSIZE - 256) hist[256 + t] = 0u;
    if (t == 0) { s_cnthi = 0u; s_ncand = 0u; s_bin = -2; }
    __syncthreads();

    // Load 16 elements/thread as keys (coalesced float4); zero the output row.
    unsigned key[16];
    const float4* src  = (const float4*)(scores + (size_t)row * LK);
    float4*       zdst = (float4*)(out + (size_t)row * LK);
    #pragma unroll
    for (int i = 0; i < 4; i++) {
        float4 v = __ldcs(src + t + i * 256);
        key[4 * i + 0] = fkey(v.x); key[4 * i + 1] = fkey(v.y);
        key[4 * i + 2] = fkey(v.z); key[4 * i + 3] = fkey(v.w);
    }
    const float4 z = make_float4(0.f, 0.f, 0.f, 0.f);
    #pragma unroll
    for (int i = 0; i < 4; i++) __stcs(zdst + t + i * 256, z);

    // Count above-window; histogram in-window keys (~8% of row)
    int chi = 0;
    #pragma unroll
    for (int e = 0; e < 16; e++) {
        unsigned k = key[e];
        if (k > KHI) chi++;
        else if (k >= KLO) atomicAdd(&hist[(KHI - k) >> BSHIFT], 1u);
    }
    #pragma unroll
    for (int off = 16; off; off >>= 1)
        chi += __shfl_down_sync(0xffffffffu, chi, off);
    if (lane == 0) atomicAdd(&s_cnthi, (unsigned)chi);
    __syncthreads();

    // One-warp cumulative-from-top scan over the bins (bin 0 = largest values)
    if (warp == 0) {
        const unsigned cnthi = s_cnthi;
        unsigned part = 0;
        #pragma unroll
        for (int i = 0; i < BPL; i++) part += hist[lane * BPL + i];
        unsigned pfx = part;
        #pragma unroll
        for (int s = 1; s < 32; s <<= 1) {
            unsigned v = __shfl_up_sync(0xffffffffu, pfx, s);
            if (lane >= s) pfx += v;
        }
        unsigned excl  = pfx - part;
        unsigned total = __shfl_sync(0xffffffffu, pfx, 31);
        unsigned base  = cnthi + excl;
        if (base < KSEL && base + part >= KSEL) {
            unsigned acc = base;
            #pragma unroll
            for (int i = 0; i < BPL; i++) {
                unsigned hv = hist[lane * BPL + i];
                if (acc + hv >= KSEL) { s_bin = lane * BPL + i; s_rem = (int)(KSEL - acc); break; }
                acc += hv;
            }
        }
        if (lane == 0 && (cnthi >= KSEL || cnthi + total < KSEL)) s_bin = -1; // fallback
    }
    __syncthreads();

    const int bin = s_bin;

    if (bin >= 0) {
        // Gather pivot-bin candidates (expected ~1, bin width 2^-10 in value)
        #pragma unroll
        for (int e = 0; e < 16; e++) {
            unsigned k = key[e];
            if (k <= KHI && k >= KLO && (int)((KHI - k) >> BSHIFT) == bin) {
                unsigned p = atomicAdd(&s_ncand, 1u);
                if (p < MAXCAND) cand[p] = k;
            }
        }
        __syncthreads();
        unsigned nc = s_ncand;
        if (nc <= MAXCAND) {
            const int rem = s_rem;
            if (t < (int)nc) {
                unsigned me = cand[t];
                int gcnt = 0, eq = 0;
                for (unsigned j = 0; j < nc; j++) {
                    unsigned v = cand[j];
                    gcnt += (v > me);
                    eq   += (v == me);
                }
                if (gcnt < rem && gcnt + eq >= rem) s_pivotkey = me;
            }
        } else {
            if (t == 0) s_bin = -1;   // overflow -> fallback
        }
        __syncthreads();
    }

    if (s_bin < 0) {
        // Exact fallback: MSB-first binary search on keys
        unsigned piv = 0;
        for (int bit = 31; bit >= 0; --bit) {
            unsigned candv = piv | (1u << bit);
            int c = 0;
            #pragma unroll
            for (int e = 0; e < 16; e++) c += (key[e] >= candv);
            #pragma unroll
            for (int off = 16; off; off >>= 1)
                c += __shfl_down_sync(0xffffffffu, c, off);
            if (t == 0) s_tot = 0u;
            __syncthreads();
            if (lane == 0) atomicAdd(&s_tot, (unsigned)c);
            __syncthreads();
            if (s_tot >= KSEL) piv = candv;
            __syncthreads();
        }
        if (t == 0) s_pivotkey = piv;
        __syncthreads();
    }

    const unsigned pivot = s_pivotkey;

    // Membership: element 4t+1024i+m. Per i, each thread owns 4 consecutive
    // bits; OR-merge nibbles across each 8-lane octet with 3 xor-shuffles,
    // lane(octet leader) writes the 32-bit word. No smem, no barrier.
    unsigned* mrow = g_masks + (size_t)row * WORDS;
    #pragma unroll
    for (int i = 0; i < 4; i++) {
        unsigned nib = 0;
        #pragma unroll
        for (int m = 0; m < 4; m++) nib |= (unsigned)(key[4 * i + m] >= pivot) << m;
        unsigned wv = nib << (4 * (lane & 7));
        wv |= __shfl_xor_sync(0xffffffffu, wv, 1);
        wv |= __shfl_xor_sync(0xffffffffu, wv, 2);
        wv |= __shfl_xor_sync(0xffffffffu, wv, 4);
        if ((lane & 7) == 0) mrow[32 * i + 4 * warp + (lane >> 3)] = wv;
    }
}

// ---------------------------------------------------------------------------
// Kernel 2 (fused tail): one block per head (32 blocks, always co-resident).
// Phase 1: per-head back-to-front scan (parallel across heads). Spin barrier.
// n_stop. Phase 2: per-head union. Spin barrier. Group-OR + last-row write
// (spread over 32 blocks) + density. All __syncthreads() unconditional.
// ---------------------------------------------------------------------------
__global__ void __launch_bounds__(256) k_tail(float* __restrict__ out, int write_density) {
    const int h = blockIdx.x;          // 0..31
    const int g = h / GS;
    const int t = threadIdx.x;
    const int lane = t & 31, warp = t >> 5;
    __shared__ int s_found, s_cnt, s_nstop;
    __shared__ int ws[8];
    __shared__ unsigned su[WORDS];

    // ---- Phase 1: nsel for head h ----
    if (t == 0) { s_found = 0; s_cnt = 0; }
    __syncthreads();
    const unsigned* base = g_masks + (size_t)h * LQ * WORDS;
    unsigned un = 0;
    for (int n = 1; n <= LQ; n++) {
        unsigned m = (t < 128) ? base[(size_t)(LQ - n) * WORDS + t] : 0u;
        int add = __popc(m & ~un);
        un |= m;
        #pragma unroll
        for (int off = 16; off; off >>= 1)
            add += __shfl_down_sync(0xffffffffu, add, off);
        if (lane == 0) ws[warp] = add;
        __syncthreads();
        if (t == 0) {
            int sum = 0;
            #pragma unroll
            for (int w = 0; w < 8; w++) sum += ws[w];
            s_cnt += sum;
            if (!s_found && s_cnt >= THRESH) s_found = n;
        }
        __syncthreads();
        if (s_found) break;            // uniform: decided from shared state
    }
    if (t == 0) {
        g_nsel[h] = s_found ? s_found : NOT_CHOSEN;
        __threadfence();
        atomicExch(&g_done[h], 1);
    }

    // ---- Global barrier 1 (32 co-resident blocks) ----
    if (t < H) {
        volatile int* vd = g_done;
        while (vd[t] == 0) {}
    }
    __syncthreads();
    __threadfence();

    // n_stop from all heads (warp 0)
    if (warp == 0) {
        int v  = g_nsel[lane];
        int ch = (v < NOT_CHOSEN) ? 1 : 0;
        int mx = ch ? v : 1;
        #pragma unroll
        for (int off = 16; off; off >>= 1) {
            ch = min(ch, __shfl_down_sync(0xffffffffu, ch, off));
            mx = max(mx, __shfl_down_sync(0xffffffffu, mx, off));
        }
        if (lane == 0) s_nstop = ch ? mx : LQ;
    }
    __syncthreads();

    // ---- Phase 2: union of last n_stop rows of head h ----
    const int ns = s_nstop;
    if (t < 128) {
        unsigned u = 0;
        for (int n = 1; n <= ns; n++)
            u |= base[(size_t)(LQ - n) * WORDS + t];
        g_hunion[h * WORDS + t] = u;
    }
    __threadfence();
    __syncthreads();
    if (t == 0) atomicExch(&g_done2[h], 1);

    // ---- Global barrier 2 ----
    if (t < H) {
        volatile int* vd = g_done2;
        while (vd[t] == 0) {}
    }
    __syncthreads();
    __threadfence();

    // Group-OR for this head's group
    if (t < 128) {
        unsigned gu = g_hunion[(g * GS + 0) * WORDS + t]
                    | g_hunion[(g * GS + 1) * WORDS + t]
                    | g_hunion[(g * GS + 2) * WORDS + t]
                    | g_hunion[(g * GS + 3) * WORDS + t];
        su[t] = gu;
        int c = __popc(gu);
        #pragma unroll
        for (int off = 16; off; off >>= 1)
            c += __shfl_down_sync(0xffffffffu, c, off);
        if (lane == 0) ws[warp] = c;
    }
    __syncthreads();

    // Last-row values for head h (float4 stores, 16 KB per block)
    const float MINV = -3.402823466e38f;  // finfo(float32).min
    float* orow = out + ((size_t)h * LQ + (LQ - 1)) * LK;
    #pragma unroll
    for (int i = 0; i < 4; i++) {
        int c4 = t + i * 256;              // float4 index; cols 4*c4..4*c4+3
        unsigned w = su[c4 >> 3];
        float4 v;
        v.x = ((w >> ((4 * c4 + 0) & 31)) & 1u) ? 0.0f : MINV;
        v.y = ((w >> ((4 * c4 + 1) & 31)) & 1u) ? 0.0f : MINV;
        v.z = ((w >> ((4 * c4 + 2) & 31)) & 1u) ? 0.0f : MINV;
        v.w = ((w >> ((4 * c4 + 3) & 31)) & 1u) ? 0.0f : MINV;
        ((float4*)orow)[c4] = v;
    }

    // Density: one block per group publishes; block 0 aggregates
    if (write_density) {
        if ((h & (GS - 1)) == 0 && t == 0) {
            g_gcnt[g] = GS * (ws[0] + ws[1] + ws[2] + ws[3]);
            __threadfence();
            atomicExch(&g_done3[g], 1);
        }
        if (h == 0) {
            if (t < NG) {
                volatile int* vd = g_done3;
                while (vd[t] == 0) {}
            }
            __syncthreads();
            __threadfence();
            if (t == 0) {
                int total = 0;
                #pragma unroll
                for (int i = 0; i < NG; i++) total += g_gcnt[i];
                out[(size_t)H * LQ * LK] = (float)total / (float)(H * LK);
            }
        }
    }
}

// ---------------------------------------------------------------------------
extern "C" void kernel_launch(void* const* d_in, const int* in_sizes, int n_in,
                              void* d_out, int out_size) {
    const float* scores = (const float*)d_in[0];
    float* out = (float*)d_out;

    k_topk<<<H * LQ, 256>>>(scores, out);   // also zeros output rows + resets flags
    k_tail<<<H, 256>>>(out, out_size > H * LQ * LK ? 1 : 0);
}